// round 6
// baseline (speedup 1.0000x reference)
#include <cuda_runtime.h>
#include <math.h>

#define DD      64
#define TRI     2080          // 64*65/2
#define NT      288           // 9 warps = 36 tiles x 8 slices, zero idle lanes
#define NW      (NT / 32)     // 9
#define CHUNK   32            // nodes per smem chunk
#define RSTRIDE 68            // padded row stride (floats); 68*4=272B, 16B-aligned rows
#define NSL     8             // k-slices per tile
#define IMPCAP  512           // smem imp capacity per graph

#define MAX_M  100000
#define MAX_G  1024

__device__ float g_imp[MAX_M];         // fallback only (n > IMPCAP)
__device__ int   g_start[MAX_G + 1];

// ---------------------------------------------------------------------------
// Segment boundaries from sorted batch, with inline int64/int32 dtype sniff.
// int64 batch (values < 2^31): every odd 32-bit word is 0.
// int32 sorted batch: sampled odd words across the array are > 0.
// ---------------------------------------------------------------------------
__global__ void k_bounds(const void* __restrict__ batch, int M, int G) {
    __shared__ int s_is64;
    const int* b32 = (const int*)batch;
    const long long* b64 = (const long long*)batch;

    if (threadIdx.x == 0) {
        int anynz = 0;
#pragma unroll
        for (int k = 1; k < 32; ++k) {
            long long pos = ((long long)k * M) / 32;
            int idx = (int)(pos | 1);           // odd word index
            if (idx < M) anynz |= (b32[idx] != 0);
        }
        s_is64 = (anynz == 0) ? 1 : 0;
    }
    __syncthreads();
    int is64 = s_is64;

    int m = blockIdx.x * blockDim.x + threadIdx.x;
    if (m >= M) return;
    int b  = is64 ? (int)b64[m] : b32[m];
    int pb;
    if (m == 0) pb = -1;
    else        pb = is64 ? (int)b64[m - 1] : b32[m - 1];
    if (b  < 0) b  = 0; if (b  >= G) b  = G - 1;
    if (pb < -1) pb = -1; if (pb >= G) pb = G - 1;
    for (int g = pb + 1; g <= b; ++g) g_start[g] = m;
    if (m == M - 1) {
        for (int g = b + 1; g <= G; ++g) g_start[g] = M;
    }
}

// ---------------------------------------------------------------------------
// Fused per-graph kernel: imp -> softmax stats -> weighted SYRK -> triu out.
// 36 upper 8x8 tiles x 8 k-slices = 288 threads = 9 full warps (no idle lanes).
// simp[] ends up holding sqrt(e_k); smem rows hold sqrt(e_k)*x_k so the pure
// FFMA a*b carries e_k. Final scale by 1/denom at writeout.
// ---------------------------------------------------------------------------
__global__ __launch_bounds__(NT, 2)
void k_syrk(const float* __restrict__ x, const float* __restrict__ w,
            const float* __restrict__ bias, float* __restrict__ out, int G) {
    __shared__ float sz[2][CHUNK * RSTRIDE];
    __shared__ float simp[IMPCAP];
    __shared__ float sred[NW];
    __shared__ float sbr[2];

    int g    = blockIdx.x;
    int tid  = threadIdx.x;
    int wid  = tid >> 5;
    int lane = tid & 31;
    int s    = g_start[g];
    int n    = g_start[g + 1] - s;
    bool useSm = (n <= IMPCAP);

    // ---- phase 1: raw imp for this graph's nodes (warp per node) ----
    for (int i = wid; i < n; i += NW) {
        const float* xr = x + ((size_t)(s + i) << 6);
        float v = xr[lane] * __ldg(w + lane) + xr[lane + 32] * __ldg(w + lane + 32);
#pragma unroll
        for (int o = 16; o; o >>= 1) v += __shfl_xor_sync(0xFFFFFFFFu, v, o);
        if (lane == 0) {
            float val = v + __ldg(bias);
            if (useSm) simp[i] = val;
            else       g_imp[s + i] = val;
        }
    }
    __syncthreads();

    // ---- phase 2: segment max ----
    float mx = -3.402823466e38f;
    for (int i = tid; i < n; i += NT)
        mx = fmaxf(mx, useSm ? simp[i] : g_imp[s + i]);
#pragma unroll
    for (int o = 16; o; o >>= 1) mx = fmaxf(mx, __shfl_xor_sync(0xFFFFFFFFu, mx, o));
    if (lane == 0) sred[wid] = mx;
    __syncthreads();
    if (tid == 0) {
        float m2 = sred[0];
#pragma unroll
        for (int i = 1; i < NW; ++i) m2 = fmaxf(m2, sred[i]);
        sbr[0] = m2;
    }
    __syncthreads();
    mx = sbr[0];

    // ---- phase 3: denom; overwrite imp slot with sqrt(e) (same-thread RW) ----
    float sum = 0.f;
    for (int i = tid; i < n; i += NT) {
        float v  = useSm ? simp[i] : g_imp[s + i];
        float sq = expf(0.5f * (v - mx));
        sum += sq * sq;
        if (useSm) simp[i] = sq;
        else       g_imp[s + i] = sq;
    }
#pragma unroll
    for (int o = 16; o; o >>= 1) sum += __shfl_xor_sync(0xFFFFFFFFu, sum, o);
    if (lane == 0) sred[wid] = sum;
    __syncthreads();
    if (tid == 0) {
        float t = 0.f;
#pragma unroll
        for (int i = 0; i < NW; ++i) t += sred[i];
        sbr[1] = (n > 0) ? (1.0f / t) : 0.0f;
    }
    __syncthreads();
    float inv_denom = sbr[1];

    // ---- tile mapping: tile = tid>>3 in [0,36), slice = tid&7 ----
    int tile  = tid >> 3;
    int slice = tid & 7;
    int ti = 0, tmp = tile;
#pragma unroll
    for (int r = 0; r < 8; ++r) {
        int rl = 8 - r;
        if (ti == r && tmp >= rl) { tmp -= rl; ti = r + 1; }
    }
    int tj = ti + tmp;

    float acc[8][8];
#pragma unroll
    for (int i = 0; i < 8; ++i)
#pragma unroll
        for (int j = 0; j < 8; ++j) acc[i][j] = 0.f;

    int nch = (n + CHUNK - 1) / CHUNK;

    // chunk loader: rows scaled by precomputed sqrt(e), zero tail
#define LOAD_CHUNK(cidx, buf)                                                  \
    do {                                                                       \
        int _base = (cidx) * CHUNK;                                            \
        for (int q = tid; q < CHUNK * 16; q += NT) {                           \
            int _row = q >> 4, _c4 = q & 15;                                   \
            float4 _v = make_float4(0.f, 0.f, 0.f, 0.f);                       \
            int _node = _base + _row;                                          \
            if (_node < n) {                                                   \
                float _sq = useSm ? simp[_node] : g_imp[s + _node];            \
                _v = __ldg((const float4*)(x + ((size_t)(s + _node) << 6)) + _c4); \
                _v.x *= _sq; _v.y *= _sq; _v.z *= _sq; _v.w *= _sq;            \
            }                                                                  \
            *(float4*)&sz[buf][_row * RSTRIDE + _c4 * 4] = _v;                 \
        }                                                                      \
    } while (0)

    if (nch > 0) LOAD_CHUNK(0, 0);

    for (int c = 0; c < nch; ++c) {
        __syncthreads();                       // chunk c visible; buf (c+1)&1 free
        if (c + 1 < nch) LOAD_CHUNK(c + 1, (c + 1) & 1);

        const float* zb = sz[c & 1];
#pragma unroll
        for (int k = 0; k < CHUNK / NSL; ++k) {
            int kk = k * NSL + slice;
            const float* row = zb + kk * RSTRIDE;
            float4 a0 = *(const float4*)&row[ti * 8];
            float4 a1 = *(const float4*)&row[ti * 8 + 4];
            float4 b0 = *(const float4*)&row[tj * 8];
            float4 b1 = *(const float4*)&row[tj * 8 + 4];
            float a[8] = { a0.x, a0.y, a0.z, a0.w, a1.x, a1.y, a1.z, a1.w };
            float b[8] = { b0.x, b0.y, b0.z, b0.w, b1.x, b1.y, b1.z, b1.w };
#pragma unroll
            for (int i = 0; i < 8; ++i)
#pragma unroll
                for (int j = 0; j < 8; ++j)
                    acc[i][j] += a[i] * b[j];
        }
    }

    // ---- slice combine (shfl xor 1,2,4 — slices live in lane bits 0-2) ----
#pragma unroll
    for (int i = 0; i < 8; ++i)
#pragma unroll
        for (int j = 0; j < 8; ++j) {
            acc[i][j] += __shfl_xor_sync(0xFFFFFFFFu, acc[i][j], 1);
            acc[i][j] += __shfl_xor_sync(0xFFFFFFFFu, acc[i][j], 2);
            acc[i][j] += __shfl_xor_sync(0xFFFFFFFFu, acc[i][j], 4);
        }

    if (slice == 0) {
        float* og = out + (size_t)g * TRI;
#pragma unroll
        for (int i = 0; i < 8; ++i) {
            int gi = ti * 8 + i;
            int base = gi * DD - (gi * (gi - 1)) / 2 - gi;  // + gj -> triu idx
#pragma unroll
            for (int j = 0; j < 8; ++j) {
                int gj = tj * 8 + j;
                if (gj >= gi) og[base + gj] = acc[i][j] * inv_denom;
            }
        }
    }
#undef LOAD_CHUNK
}

// ---------------------------------------------------------------------------
// Launch. Inputs identified BY SIZE (order-invariant):
//   att_b: size 1; att_w: size 64; batch: size*64 == size of x; edge: leftover.
// ---------------------------------------------------------------------------
extern "C" void kernel_launch(void* const* d_in, const int* in_sizes, int n_in,
                              void* d_out, int out_size) {
    int ib = -1, iw = -1, ibatch = -1, ix = -1;
    for (int i = 0; i < n_in; ++i) {
        if (in_sizes[i] == 1)       ib = i;
        else if (in_sizes[i] == DD) iw = i;
    }
    for (int i = 0; i < n_in && ibatch < 0; ++i) {
        if (i == ib || i == iw) continue;
        for (int j = 0; j < n_in; ++j) {
            if (j == i || j == ib || j == iw) continue;
            if ((long long)in_sizes[i] * DD == (long long)in_sizes[j]) {
                ibatch = i; ix = j; break;
            }
        }
    }
    if (ib < 0 || iw < 0 || ibatch < 0 || ix < 0) {  // fallback: reference order
        ix = 0; iw = 1; ib = 2; ibatch = 3;
    }

    const float* x    = (const float*)d_in[ix];
    const float* w    = (const float*)d_in[iw];
    const float* bias = (const float*)d_in[ib];
    const void*  batch = d_in[ibatch];

    int M = in_sizes[ix] / DD;
    int G = out_size / TRI;
    float* out = (float*)d_out;

    k_bounds<<<(M + 255) / 256, 256>>>(batch, M, G);
    k_syrk<<<G, NT>>>(x, w, bias, out, G);
}